// round 2
// baseline (speedup 1.0000x reference)
#include <cuda_runtime.h>
#include <cstdint>

// Problem constants
#define BD   32
#define DDIM 256
#define HW   1024           // 32*32
#define NN   32768          // B*H*W rows
#define KK   1024           // codebook size
#define NZ   8388608        // B*D*H*W output elements of z_q
#define GATHER_BLOCKS 8192  // NZ / 1024

// Device scratch (no allocations allowed)
__device__ int   g_idx[NN];
__device__ float g_ek2[KK];
__device__ float g_zn2[NN];
__device__ float g_partial[GATHER_BLOCKS];

// ---------------- packed fp32x2 helpers ----------------
static __device__ __forceinline__ unsigned long long pack2(float x, float y) {
    unsigned long long r;
    asm("mov.b64 %0, {%1, %2};" : "=l"(r) : "f"(x), "f"(y));
    return r;
}
static __device__ __forceinline__ float2 unpack2(unsigned long long v) {
    float2 f;
    asm("mov.b64 {%0, %1}, %2;" : "=f"(f.x), "=f"(f.y) : "l"(v));
    return f;
}
static __device__ __forceinline__ void fma2(unsigned long long &d,
                                            unsigned long long a,
                                            unsigned long long b) {
    asm("fma.rn.f32x2 %0, %1, %2, %0;" : "+l"(d) : "l"(a), "l"(b));
}

// ---------------- cp.async helpers ----------------
static __device__ __forceinline__ void cp16(void* smem_dst, const void* gsrc) {
    unsigned s = (unsigned)__cvta_generic_to_shared(smem_dst);
    asm volatile("cp.async.cg.shared.global [%0], [%1], 16;" :: "r"(s), "l"(gsrc));
}
static __device__ __forceinline__ void cp4(void* smem_dst, const void* gsrc) {
    unsigned s = (unsigned)__cvta_generic_to_shared(smem_dst);
    asm volatile("cp.async.ca.shared.global [%0], [%1], 4;" :: "r"(s), "l"(gsrc));
}
static __device__ __forceinline__ void cp_commit() {
    asm volatile("cp.async.commit_group;");
}
template <int N>
static __device__ __forceinline__ void cp_wait() {
    asm volatile("cp.async.wait_group %0;" :: "n"(N));
}

// ---------------- kernel A: ||e_k||^2 ----------------
// (enters the distance ~2 bits below ULP(256); any accurate order works)
__global__ void ek2_kernel(const float* __restrict__ emb) {
    int k = blockIdx.x * 8 + (threadIdx.x >> 5);
    int lane = threadIdx.x & 31;
    const float* row = emb + (size_t)k * DDIM;
    float s = 0.f;
#pragma unroll
    for (int i = 0; i < 8; ++i) {
        float v = row[lane + 32 * i];
        s = fmaf(v, v, s);
    }
#pragma unroll
    for (int o = 16; o; o >>= 1) s += __shfl_down_sync(0xffffffffu, s, o);
    if (lane == 0) g_ek2[k] = s;
}

// ---------------- kernel A2: ||z_n||^2, replicating XLA-CPU scalar reduce ----
// Sequential d = 0..255, separate mul and add roundings (no fma, no reassoc).
__global__ void zn2_kernel(const float* __restrict__ z) {
    int n  = blockIdx.x * 256 + threadIdx.x;   // n = b*1024 + hw
    int b  = n >> 10;
    int hw = n & 1023;
    const float* p = z + (size_t)b * (DDIM * HW) + hw;
    float acc = 0.f;
#pragma unroll 8
    for (int d = 0; d < DDIM; ++d) {
        float v = p[(size_t)d * HW];
        acc = __fadd_rn(acc, __fmul_rn(v, v));
    }
    g_zn2[n] = acc;
}

// ---------------- kernel B: fused distance GEMM + argmin ----------------
// dist_k = fl( fl(zn2 + ek2) - 2 * dot ), dot = sequential fp32 fma chain over d
// (bit-matching Eigen gebp). Argmin with lowest-index tie-break.
__global__ void __launch_bounds__(256, 2)
vq_argmin_kernel(const float* __restrict__ z, const float* __restrict__ emb) {
    __shared__ __align__(16) float Zs[2][16][128];   // 16 KB
    __shared__ __align__(16) float Es[2][16][130];   // 16.25 KB (pad -> conflict-free)
    __shared__ float ek2s[KK];                       // 4 KB
    __shared__ float zn2s[128];

    const int tid = threadIdx.x;
    const int tx  = tid & 15;
    const int ty  = tid >> 4;
    const int m0  = blockIdx.x * 128;
    const int b   = m0 >> 10;      // HW = 1024, blocks never straddle a batch
    const int hw0 = m0 & 1023;
    const float* zb = z + (size_t)b * (DDIM * HW);

#pragma unroll
    for (int r = 0; r < 4; ++r) ek2s[tid + 256 * r] = g_ek2[tid + 256 * r];
    if (tid < 128) zn2s[tid] = g_zn2[m0 + tid];
    __syncthreads();

    float znr[8];
#pragma unroll
    for (int m = 0; m < 8; ++m) znr[m] = zn2s[tx * 8 + m];

    float bestv[8];
    int   besti[8];
#pragma unroll
    for (int m = 0; m < 8; ++m) { bestv[m] = 3.4e38f; besti[m] = 0; }

#pragma unroll 1
    for (int kt = 0; kt < 8; ++kt) {
        const int k0 = kt * 128;

        unsigned long long acc[4][8];
#pragma unroll
        for (int j = 0; j < 4; ++j)
#pragma unroll
            for (int m = 0; m < 8; ++m) acc[j][m] = 0ull;

        auto loadTile = [&](int dc, int bufw) {
            const int d0 = dc * 16;
#pragma unroll
            for (int r = 0; r < 2; ++r) {               // Z: 512 float4
                int i4 = tid + 256 * r;
                int dd = i4 >> 5;
                int mq = (i4 & 31) << 2;
                cp16(&Zs[bufw][dd][mq], zb + (size_t)(d0 + dd) * HW + hw0 + mq);
            }
#pragma unroll
            for (int r = 0; r < 8; ++r) {               // E: 2048 floats, transposed store
                int l  = tid + 256 * r;
                int dd = l & 15;
                int k  = l >> 4;
                cp4(&Es[bufw][dd][k], emb + (size_t)(k0 + k) * DDIM + d0 + dd);
            }
        };

        loadTile(0, 0);
        cp_commit();
        int buf = 0;
#pragma unroll 1
        for (int dc = 0; dc < 16; ++dc) {
            if (dc < 15) {
                loadTile(dc + 1, buf ^ 1);
                cp_commit();
                cp_wait<1>();
            } else {
                cp_wait<0>();
            }
            __syncthreads();

            const float (*Zc)[128] = Zs[buf];
            const float (*Ec)[130] = Es[buf];
#pragma unroll
            for (int dd = 0; dd < 16; ++dd) {           // d ascending 0..255 overall
                float4 za = *(const float4*)&Zc[dd][tx * 8];
                float4 zc = *(const float4*)&Zc[dd][tx * 8 + 4];
                unsigned long long zd[8];
                zd[0] = pack2(za.x, za.x); zd[1] = pack2(za.y, za.y);
                zd[2] = pack2(za.z, za.z); zd[3] = pack2(za.w, za.w);
                zd[4] = pack2(zc.x, zc.x); zd[5] = pack2(zc.y, zc.y);
                zd[6] = pack2(zc.z, zc.z); zd[7] = pack2(zc.w, zc.w);
                unsigned long long ap[4];
#pragma unroll
                for (int j = 0; j < 4; ++j)
                    ap[j] = *(const unsigned long long*)&Ec[dd][2 * ty + 32 * j];
#pragma unroll
                for (int j = 0; j < 4; ++j)
#pragma unroll
                    for (int m = 0; m < 8; ++m) fma2(acc[j][m], ap[j], zd[m]);
            }
            __syncthreads();
            buf ^= 1;
        }

        // fold this k-tile: dist = fl( fl(zn2 + ek2) - 2*dot ), reference rounding
#pragma unroll
        for (int j = 0; j < 4; ++j) {
            const int kk = k0 + 2 * ty + 32 * j;
            const float e0 = ek2s[kk];
            const float e1 = ek2s[kk + 1];
#pragma unroll
            for (int m = 0; m < 8; ++m) {
                float2 a2 = unpack2(acc[j][m]);
                float t0 = __fadd_rn(znr[m], e0);
                float t1 = __fadd_rn(znr[m], e1);
                float v0 = fmaf(-2.f, a2.x, t0);
                float v1 = fmaf(-2.f, a2.y, t1);
                if (v0 < bestv[m] || (v0 == bestv[m] && kk < besti[m])) {
                    bestv[m] = v0; besti[m] = kk;
                }
                if (v1 < bestv[m] || (v1 == bestv[m] && (kk + 1) < besti[m])) {
                    bestv[m] = v1; besti[m] = kk + 1;
                }
            }
        }
    }

    // cross-ty reduction (reuse Zs/Es smem; all cp.async drained)
    float* Rv = &Zs[0][0][0];      // 16 x 128 floats
    int*   Ri = (int*)&Es[0][0][0];
    __syncthreads();
#pragma unroll
    for (int m = 0; m < 8; ++m) {
        Rv[ty * 128 + tx * 8 + m] = bestv[m];
        Ri[ty * 128 + tx * 8 + m] = besti[m];
    }
    __syncthreads();
    if (tid < 128) {
        float bv = Rv[tid];
        int   bi = Ri[tid];
#pragma unroll
        for (int t = 1; t < 16; ++t) {
            float v = Rv[t * 128 + tid];
            int   i = Ri[t * 128 + tid];
            if (v < bv || (v == bv && i < bi)) { bv = v; bi = i; }
        }
        g_idx[m0 + tid] = bi;
    }
}

// ---------------- kernel C: gather z_q (straight-through) + loss partials ----
__global__ void gather_kernel(const float* __restrict__ z,
                              const float* __restrict__ emb,
                              float* __restrict__ out) {
    __shared__ float red[256];
    const int base = blockIdx.x * 1024 + threadIdx.x;
    float s = 0.f;
#pragma unroll
    for (int r = 0; r < 4; ++r) {
        int i   = base + 256 * r;
        int bq  = i >> 18;         // / (D*HW) = / 262144
        int rem = i & 262143;
        int d   = rem >> 10;       // / HW
        int hw  = rem & 1023;
        int n   = (bq << 10) | hw;
        float q  = emb[(size_t)g_idx[n] * DDIM + d];
        float zv = z[i];
        float df = __fadd_rn(q, -zv);          // fl(z_q - z)
        out[i] = __fadd_rn(zv, df);            // fl(z + fl(z_q - z)) — straight-through
        s = fmaf(df, df, s);
    }
    red[threadIdx.x] = s;
    __syncthreads();
#pragma unroll
    for (int o = 128; o; o >>= 1) {
        if (threadIdx.x < o) red[threadIdx.x] += red[threadIdx.x + o];
        __syncthreads();
    }
    if (threadIdx.x == 0) g_partial[blockIdx.x] = red[0];
}

// ---------------- kernel D: finalize loss (deterministic tree reduce) --------
__global__ void finalize_kernel(float* __restrict__ out) {
    __shared__ float red[256];
    float s = 0.f;
#pragma unroll
    for (int r = 0; r < GATHER_BLOCKS / 256; ++r)
        s += g_partial[threadIdx.x + 256 * r];
    red[threadIdx.x] = s;
    __syncthreads();
#pragma unroll
    for (int o = 128; o; o >>= 1) {
        if (threadIdx.x < o) red[threadIdx.x] += red[threadIdx.x + o];
        __syncthreads();
    }
    if (threadIdx.x == 0) {
        float q = red[0] / (float)NZ;          // /2^23 is exact
        out[NZ] = __fadd_rn(q, 0.25f * q);     // loss = q_latent + 0.25*e_latent
    }
}

// ---------------- kernel E: indices as float ----------------
__global__ void idx_out_kernel(float* __restrict__ out) {
    int n = blockIdx.x * 256 + threadIdx.x;
    out[NZ + 1 + n] = (float)g_idx[n];
}

extern "C" void kernel_launch(void* const* d_in, const int* in_sizes, int n_in,
                              void* d_out, int out_size) {
    const float* a0 = (const float*)d_in[0];
    const float* a1 = (const float*)d_in[1];
    // identify inputs by element count (z: 8388608, emb: 262144)
    const float* z;
    const float* emb;
    if (in_sizes[0] == NZ) { z = a0; emb = a1; }
    else                   { z = a1; emb = a0; }
    float* out = (float*)d_out;

    ek2_kernel<<<128, 256>>>(emb);
    zn2_kernel<<<NN / 256, 256>>>(z);
    vq_argmin_kernel<<<256, 256>>>(z, emb);
    gather_kernel<<<GATHER_BLOCKS, 256>>>(z, emb, out);
    if (out_size > NZ)            finalize_kernel<<<1, 256>>>(out);
    if (out_size >= NZ + 1 + NN)  idx_out_kernel<<<NN / 256, 256>>>(out);
}

// round 3
// speedup vs baseline: 1.0960x; 1.0960x over previous
#include <cuda_runtime.h>
#include <cstdint>

// Problem constants
#define BD   32
#define DDIM 256
#define HW   1024           // 32*32
#define NN   32768          // B*H*W rows
#define KK   1024           // codebook size
#define NZ   8388608        // B*D*H*W output elements of z_q
#define GATHER_BLOCKS 1024  // NN / 32

// Device scratch (no allocations allowed)
__device__ int   g_idx[NN];
__device__ float g_ek2[KK];
__device__ float g_zn2[NN];
__device__ float g_partial[GATHER_BLOCKS];

// ---------------- packed fp32x2 helpers ----------------
static __device__ __forceinline__ unsigned long long pack2(float x, float y) {
    unsigned long long r;
    asm("mov.b64 %0, {%1, %2};" : "=l"(r) : "f"(x), "f"(y));
    return r;
}
static __device__ __forceinline__ float2 unpack2(unsigned long long v) {
    float2 f;
    asm("mov.b64 {%0, %1}, %2;" : "=f"(f.x), "=f"(f.y) : "l"(v));
    return f;
}
static __device__ __forceinline__ void fma2(unsigned long long &d,
                                            unsigned long long a,
                                            unsigned long long b) {
    asm("fma.rn.f32x2 %0, %1, %2, %0;" : "+l"(d) : "l"(a), "l"(b));
}

// ---------------- cp.async helpers ----------------
static __device__ __forceinline__ void cp16(void* smem_dst, const void* gsrc) {
    unsigned s = (unsigned)__cvta_generic_to_shared(smem_dst);
    asm volatile("cp.async.cg.shared.global [%0], [%1], 16;" :: "r"(s), "l"(gsrc));
}
static __device__ __forceinline__ void cp_commit() {
    asm volatile("cp.async.commit_group;");
}
template <int N>
static __device__ __forceinline__ void cp_wait() {
    asm volatile("cp.async.wait_group %0;" :: "n"(N));
}

// ---------------- kernel A: ||e_k||^2 ----------------
__global__ void ek2_kernel(const float* __restrict__ emb) {
    int k = blockIdx.x * 8 + (threadIdx.x >> 5);
    int lane = threadIdx.x & 31;
    const float* row = emb + (size_t)k * DDIM;
    float s = 0.f;
#pragma unroll
    for (int i = 0; i < 8; ++i) {
        float v = row[lane + 32 * i];
        s = fmaf(v, v, s);
    }
#pragma unroll
    for (int o = 16; o; o >>= 1) s += __shfl_down_sync(0xffffffffu, s, o);
    if (lane == 0) g_ek2[k] = s;
}

// ---------------- kernel A2: ||z_n||^2, XLA-CPU scalar reduce order ----------
__global__ void zn2_kernel(const float* __restrict__ z) {
    int n  = blockIdx.x * 256 + threadIdx.x;   // n = b*1024 + hw
    int b  = n >> 10;
    int hw = n & 1023;
    const float* p = z + (size_t)b * (DDIM * HW) + hw;
    float acc = 0.f;
#pragma unroll 8
    for (int d = 0; d < DDIM; ++d) {
        float v = p[(size_t)d * HW];
        acc = __fadd_rn(acc, __fmul_rn(v, v));
    }
    g_zn2[n] = acc;
}

// ---------------- kernel B: fused distance GEMM + argmin ----------------
// Thread (tx,ty): m = 2*tx + 32*p (+h), p=0..3 (m packed in f32x2 lanes);
//                 k = ty + 16*j, j=0..7.
// dot = sequential fp32 fma chain over d (bit-matching Eigen gebp).
// dist = fl( fl(zn2 + ek2) - 2*dot ); argmin, lowest-index tie-break.
__global__ void __launch_bounds__(256, 2)
vq_argmin_kernel(const float* __restrict__ z, const float* __restrict__ emb) {
    __shared__ __align__(16) float Zs[2][16][128];   // 16 KB, [dd][m]
    __shared__ __align__(16) float Es[2][128][16];   // 16 KB, [k][dd] (row-major, cp16-friendly)
    __shared__ float ek2s[KK];                       // 4 KB
    __shared__ float zn2s[128];

    const int tid = threadIdx.x;
    const int tx  = tid & 15;
    const int ty  = tid >> 4;
    const int m0  = blockIdx.x * 128;
    const int b   = m0 >> 10;      // blocks never straddle a batch
    const int hw0 = m0 & 1023;
    const float* zb = z + (size_t)b * (DDIM * HW);

#pragma unroll
    for (int r = 0; r < 4; ++r) ek2s[tid + 256 * r] = g_ek2[tid + 256 * r];
    if (tid < 128) zn2s[tid] = g_zn2[m0 + tid];
    __syncthreads();

    float znr[8];
#pragma unroll
    for (int p = 0; p < 4; ++p) {
        znr[2 * p]     = zn2s[2 * tx + 32 * p];
        znr[2 * p + 1] = zn2s[2 * tx + 32 * p + 1];
    }

    float bestv[8];
    int   besti[8];
#pragma unroll
    for (int q = 0; q < 8; ++q) { bestv[q] = 3.4e38f; besti[q] = 0; }

#pragma unroll 1
    for (int kt = 0; kt < 8; ++kt) {
        const int k0 = kt * 128;

        unsigned long long acc[8][4];   // [j][p]
#pragma unroll
        for (int j = 0; j < 8; ++j)
#pragma unroll
            for (int p = 0; p < 4; ++p) acc[j][p] = 0ull;

        auto loadTile = [&](int dc, int bufw) {
            const int d0 = dc * 16;
#pragma unroll
            for (int r = 0; r < 2; ++r) {               // Z: 512 float4
                int i4 = tid + 256 * r;
                int dd = i4 >> 5;
                int mq = (i4 & 31) << 2;
                cp16(&Zs[bufw][dd][mq], zb + (size_t)(d0 + dd) * HW + hw0 + mq);
            }
#pragma unroll
            for (int r = 0; r < 2; ++r) {               // E: 512 float4, row-major
                int i = tid + 256 * r;
                int k = i >> 2;
                int q = (i & 3) << 2;
                cp16(&Es[bufw][k][q], emb + (size_t)(k0 + k) * DDIM + d0 + q);
            }
        };

        loadTile(0, 0);
        cp_commit();
        int buf = 0;
#pragma unroll 1
        for (int dc = 0; dc < 16; ++dc) {
            if (dc < 15) {
                loadTile(dc + 1, buf ^ 1);
                cp_commit();
                cp_wait<1>();
            } else {
                cp_wait<0>();
            }
            __syncthreads();

#pragma unroll 4
            for (int dd = 0; dd < 16; ++dd) {           // d ascending 0..255 overall
                unsigned long long zp[4];
#pragma unroll
                for (int p = 0; p < 4; ++p)
                    zp[p] = *(const unsigned long long*)&Zs[buf][dd][2 * tx + 32 * p];
#pragma unroll
                for (int j = 0; j < 8; ++j) {
                    float e = Es[buf][ty + 16 * j][dd];
                    unsigned long long ep = pack2(e, e);
#pragma unroll
                    for (int p = 0; p < 4; ++p) fma2(acc[j][p], zp[p], ep);
                }
            }
            __syncthreads();
            buf ^= 1;
        }

        // fold this k-tile: dist = fl( fl(zn2 + ek2) - 2*dot ), reference rounding
#pragma unroll
        for (int j = 0; j < 8; ++j) {
            const int kk = k0 + ty + 16 * j;
            const float e2 = ek2s[kk];
#pragma unroll
            for (int p = 0; p < 4; ++p) {
                float2 a2 = unpack2(acc[j][p]);
                float t0 = __fadd_rn(znr[2 * p], e2);
                float v0 = fmaf(-2.f, a2.x, t0);
                if (v0 < bestv[2 * p] || (v0 == bestv[2 * p] && kk < besti[2 * p])) {
                    bestv[2 * p] = v0; besti[2 * p] = kk;
                }
                float t1 = __fadd_rn(znr[2 * p + 1], e2);
                float v1 = fmaf(-2.f, a2.y, t1);
                if (v1 < bestv[2 * p + 1] || (v1 == bestv[2 * p + 1] && kk < besti[2 * p + 1])) {
                    bestv[2 * p + 1] = v1; besti[2 * p + 1] = kk;
                }
            }
        }
    }

    // cross-ty reduction (reuse Zs/Es smem; all cp.async drained)
    float* Rv = &Zs[0][0][0];      // 16 x 128 floats
    int*   Ri = (int*)&Es[0][0][0];
    __syncthreads();
#pragma unroll
    for (int p = 0; p < 4; ++p) {
#pragma unroll
        for (int h = 0; h < 2; ++h) {
            int ml = 2 * tx + 32 * p + h;
            Rv[ty * 128 + ml] = bestv[2 * p + h];
            Ri[ty * 128 + ml] = besti[2 * p + h];
        }
    }
    __syncthreads();
    if (tid < 128) {
        float bv = Rv[tid];
        int   bi = Ri[tid];
#pragma unroll
        for (int t = 1; t < 16; ++t) {
            float v = Rv[t * 128 + tid];
            int   i = Ri[t * 128 + tid];
            if (v < bv || (v == bv && i < bi)) { bv = v; bi = i; }
        }
        g_idx[m0 + tid] = bi;
    }
}

// ---------------- kernel C: gather z_q (smem-staged, coalesced) -------------
// Block handles 32 consecutive n (same batch). Stage 32 codebook rows into
// smem coalescedly, then write out[b][d][hw] fully coalesced.
__global__ void __launch_bounds__(256)
gather_kernel(const float* __restrict__ z, const float* __restrict__ emb,
              float* __restrict__ out) {
    __shared__ float rows[32][257];   // pad -> conflict-free transpose reads
    __shared__ int   idxs[32];
    __shared__ float red[256];

    const int tid = threadIdx.x;
    const int n0  = blockIdx.x * 32;
    const int b   = n0 >> 10;
    const int hw0 = n0 & 1023;

    if (tid < 32) idxs[tid] = g_idx[n0 + tid];
    __syncthreads();

    // stage 32 rows x 256 floats (each iter: 4 rows, float4 per thread)
    const int rbase = tid >> 6;          // 0..3
    const int c4    = (tid & 63) << 2;   // 0..252
#pragma unroll
    for (int rr = 0; rr < 8; ++rr) {
        int r = rbase + rr * 4;
        float4 v = *(const float4*)(emb + (size_t)idxs[r] * DDIM + c4);
        rows[r][c4]     = v.x;
        rows[r][c4 + 1] = v.y;
        rows[r][c4 + 2] = v.z;
        rows[r][c4 + 3] = v.w;
    }
    __syncthreads();

    const int j  = tid & 31;   // hw offset within block
    const int ds = tid >> 5;   // 8 d's per pass
    float s = 0.f;
    const float* zp = z   + (size_t)b * (DDIM * HW) + hw0 + j;
    float*       op = out + (size_t)b * (DDIM * HW) + hw0 + j;
#pragma unroll 8
    for (int pass = 0; pass < 32; ++pass) {
        int d = pass * 8 + ds;
        float q  = rows[j][d];
        size_t off = (size_t)d * HW;
        float zv = zp[off];
        float df = __fadd_rn(q, -zv);      // fl(z_q - z)
        op[off] = __fadd_rn(zv, df);       // straight-through fl(z + fl(z_q - z))
        s = fmaf(df, df, s);
    }

    red[tid] = s;
    __syncthreads();
#pragma unroll
    for (int o = 128; o; o >>= 1) {
        if (tid < o) red[tid] += red[tid + o];
        __syncthreads();
    }
    if (tid == 0) g_partial[blockIdx.x] = red[0];
}

// ---------------- kernel D: finalize loss (deterministic tree reduce) --------
__global__ void finalize_kernel(float* __restrict__ out) {
    __shared__ float red[256];
    float s = 0.f;
#pragma unroll
    for (int r = 0; r < GATHER_BLOCKS / 256; ++r)
        s += g_partial[threadIdx.x + 256 * r];
    red[threadIdx.x] = s;
    __syncthreads();
#pragma unroll
    for (int o = 128; o; o >>= 1) {
        if (threadIdx.x < o) red[threadIdx.x] += red[threadIdx.x + o];
        __syncthreads();
    }
    if (threadIdx.x == 0) {
        float q = red[0] / (float)NZ;          // /2^23 exact
        out[NZ] = __fadd_rn(q, 0.25f * q);     // loss = q_latent + 0.25*e_latent
    }
}

// ---------------- kernel E: indices as float ----------------
__global__ void idx_out_kernel(float* __restrict__ out) {
    int n = blockIdx.x * 256 + threadIdx.x;
    out[NZ + 1 + n] = (float)g_idx[n];
}

extern "C" void kernel_launch(void* const* d_in, const int* in_sizes, int n_in,
                              void* d_out, int out_size) {
    const float* a0 = (const float*)d_in[0];
    const float* a1 = (const float*)d_in[1];
    const float* z;
    const float* emb;
    if (in_sizes[0] == NZ) { z = a0; emb = a1; }
    else                   { z = a1; emb = a0; }
    float* out = (float*)d_out;

    ek2_kernel<<<128, 256>>>(emb);
    zn2_kernel<<<NN / 256, 256>>>(z);
    vq_argmin_kernel<<<256, 256>>>(z, emb);
    gather_kernel<<<GATHER_BLOCKS, 256>>>(z, emb, out);
    if (out_size > NZ)            finalize_kernel<<<1, 256>>>(out);
    if (out_size >= NZ + 1 + NN)  idx_out_kernel<<<NN / 256, 256>>>(out);
}

// round 4
// speedup vs baseline: 1.0969x; 1.0008x over previous
#include <cuda_runtime.h>
#include <cstdint>

// Problem constants
#define BD   32
#define DDIM 256
#define HW   1024           // 32*32
#define NN   32768          // B*H*W rows
#define KK   1024           // codebook size
#define NZ   8388608        // B*D*H*W output elements of z_q
#define GATHER_BLOCKS 1024  // NN / 32

// Device scratch (no allocations allowed)
__device__ int   g_idx[NN];
__device__ float g_ek2[KK];
__device__ float g_zn2[NN];
__device__ float g_partial[GATHER_BLOCKS];

// ---------------- packed fp32x2 helpers ----------------
static __device__ __forceinline__ unsigned long long pack2(float x, float y) {
    unsigned long long r;
    asm("mov.b64 %0, {%1, %2};" : "=l"(r) : "f"(x), "f"(y));
    return r;
}
static __device__ __forceinline__ float2 unpack2(unsigned long long v) {
    float2 f;
    asm("mov.b64 {%0, %1}, %2;" : "=f"(f.x), "=f"(f.y) : "l"(v));
    return f;
}
static __device__ __forceinline__ void fma2(unsigned long long &d,
                                            unsigned long long a,
                                            unsigned long long b) {
    asm("fma.rn.f32x2 %0, %1, %2, %0;" : "+l"(d) : "l"(a), "l"(b));
}

// ---------------- cp.async helpers ----------------
static __device__ __forceinline__ void cp16(void* smem_dst, const void* gsrc) {
    unsigned s = (unsigned)__cvta_generic_to_shared(smem_dst);
    asm volatile("cp.async.cg.shared.global [%0], [%1], 16;" :: "r"(s), "l"(gsrc));
}
static __device__ __forceinline__ void cp_commit() {
    asm volatile("cp.async.commit_group;");
}
template <int N>
static __device__ __forceinline__ void cp_wait() {
    asm volatile("cp.async.wait_group %0;" :: "n"(N));
}

// ---------------- kernel A: ||e_k||^2 ----------------
__global__ void ek2_kernel(const float* __restrict__ emb) {
    int k = blockIdx.x * 8 + (threadIdx.x >> 5);
    int lane = threadIdx.x & 31;
    const float* row = emb + (size_t)k * DDIM;
    float s = 0.f;
#pragma unroll
    for (int i = 0; i < 8; ++i) {
        float v = row[lane + 32 * i];
        s = fmaf(v, v, s);
    }
#pragma unroll
    for (int o = 16; o; o >>= 1) s += __shfl_down_sync(0xffffffffu, s, o);
    if (lane == 0) g_ek2[k] = s;
}

// ---------------- kernel A2: ||z_n||^2, XLA-CPU scalar reduce order ----------
__global__ void zn2_kernel(const float* __restrict__ z) {
    int n  = blockIdx.x * 256 + threadIdx.x;   // n = b*1024 + hw
    int b  = n >> 10;
    int hw = n & 1023;
    const float* p = z + (size_t)b * (DDIM * HW) + hw;
    float acc = 0.f;
#pragma unroll 8
    for (int d = 0; d < DDIM; ++d) {
        float v = p[(size_t)d * HW];
        acc = __fadd_rn(acc, __fmul_rn(v, v));
    }
    g_zn2[n] = acc;
}

// ---------------- kernel B: fused distance GEMM + argmin ----------------
// Thread (tx,ty): m = 2*tx + 32*p (+h), p=0..3 (m packed in f32x2 lanes);
//                 k = ty + 16*j, j=0..7.
// dot = sequential fp32 fma chain over d (bit-matching Eigen gebp).
// dist = fl( fl(zn2 + ek2) - 2*dot ); argmin, lowest-index tie-break.
__global__ void __launch_bounds__(256, 2)
vq_argmin_kernel(const float* __restrict__ z, const float* __restrict__ emb) {
    __shared__ __align__(16) float Zs[2][16][128];   // 16 KB, [dd][m]
    __shared__ __align__(16) float Es[2][128][16];   // 16 KB, [k][dd] (row-major, cp16-friendly)
    __shared__ float ek2s[KK];                       // 4 KB
    __shared__ float zn2s[128];

    const int tid = threadIdx.x;
    const int tx  = tid & 15;
    const int ty  = tid >> 4;
    const int m0  = blockIdx.x * 128;
    const int b   = m0 >> 10;      // blocks never straddle a batch
    const int hw0 = m0 & 1023;
    const float* zb = z + (size_t)b * (DDIM * HW);

#pragma unroll
    for (int r = 0; r < 4; ++r) ek2s[tid + 256 * r] = g_ek2[tid + 256 * r];
    if (tid < 128) zn2s[tid] = g_zn2[m0 + tid];
    __syncthreads();

    float znr[8];
#pragma unroll
    for (int p = 0; p < 4; ++p) {
        znr[2 * p]     = zn2s[2 * tx + 32 * p];
        znr[2 * p + 1] = zn2s[2 * tx + 32 * p + 1];
    }

    float bestv[8];
    int   besti[8];
#pragma unroll
    for (int q = 0; q < 8; ++q) { bestv[q] = 3.4e38f; besti[q] = 0; }

#pragma unroll 1
    for (int kt = 0; kt < 8; ++kt) {
        const int k0 = kt * 128;

        unsigned long long acc[8][4];   // [j][p]
#pragma unroll
        for (int j = 0; j < 8; ++j)
#pragma unroll
            for (int p = 0; p < 4; ++p) acc[j][p] = 0ull;

        auto loadTile = [&](int dc, int bufw) {
            const int d0 = dc * 16;
#pragma unroll
            for (int r = 0; r < 2; ++r) {               // Z: 512 float4
                int i4 = tid + 256 * r;
                int dd = i4 >> 5;
                int mq = (i4 & 31) << 2;
                cp16(&Zs[bufw][dd][mq], zb + (size_t)(d0 + dd) * HW + hw0 + mq);
            }
#pragma unroll
            for (int r = 0; r < 2; ++r) {               // E: 512 float4, row-major
                int i = tid + 256 * r;
                int k = i >> 2;
                int q = (i & 3) << 2;
                cp16(&Es[bufw][k][q], emb + (size_t)(k0 + k) * DDIM + d0 + q);
            }
        };

        loadTile(0, 0);
        cp_commit();
        int buf = 0;
#pragma unroll 1
        for (int dc = 0; dc < 16; ++dc) {
            if (dc < 15) {
                loadTile(dc + 1, buf ^ 1);
                cp_commit();
                cp_wait<1>();
            } else {
                cp_wait<0>();
            }
            __syncthreads();

#pragma unroll 4
            for (int dd = 0; dd < 16; ++dd) {           // d ascending 0..255 overall
                unsigned long long zp[4];
#pragma unroll
                for (int p = 0; p < 4; ++p)
                    zp[p] = *(const unsigned long long*)&Zs[buf][dd][2 * tx + 32 * p];
#pragma unroll
                for (int j = 0; j < 8; ++j) {
                    float e = Es[buf][ty + 16 * j][dd];
                    unsigned long long ep = pack2(e, e);
#pragma unroll
                    for (int p = 0; p < 4; ++p) fma2(acc[j][p], zp[p], ep);
                }
            }
            __syncthreads();
            buf ^= 1;
        }

        // fold this k-tile: dist = fl( fl(zn2 + ek2) - 2*dot ), reference rounding
#pragma unroll
        for (int j = 0; j < 8; ++j) {
            const int kk = k0 + ty + 16 * j;
            const float e2 = ek2s[kk];
#pragma unroll
            for (int p = 0; p < 4; ++p) {
                float2 a2 = unpack2(acc[j][p]);
                float t0 = __fadd_rn(znr[2 * p], e2);
                float v0 = fmaf(-2.f, a2.x, t0);
                if (v0 < bestv[2 * p] || (v0 == bestv[2 * p] && kk < besti[2 * p])) {
                    bestv[2 * p] = v0; besti[2 * p] = kk;
                }
                float t1 = __fadd_rn(znr[2 * p + 1], e2);
                float v1 = fmaf(-2.f, a2.y, t1);
                if (v1 < bestv[2 * p + 1] || (v1 == bestv[2 * p + 1] && kk < besti[2 * p + 1])) {
                    bestv[2 * p + 1] = v1; besti[2 * p + 1] = kk;
                }
            }
        }
    }

    // cross-ty reduction (reuse Zs/Es smem; all cp.async drained)
    float* Rv = &Zs[0][0][0];      // 16 x 128 floats
    int*   Ri = (int*)&Es[0][0][0];
    __syncthreads();
#pragma unroll
    for (int p = 0; p < 4; ++p) {
#pragma unroll
        for (int h = 0; h < 2; ++h) {
            int ml = 2 * tx + 32 * p + h;
            Rv[ty * 128 + ml] = bestv[2 * p + h];
            Ri[ty * 128 + ml] = besti[2 * p + h];
        }
    }
    __syncthreads();
    if (tid < 128) {
        float bv = Rv[tid];
        int   bi = Ri[tid];
#pragma unroll
        for (int t = 1; t < 16; ++t) {
            float v = Rv[t * 128 + tid];
            int   i = Ri[t * 128 + tid];
            if (v < bv || (v == bv && i < bi)) { bv = v; bi = i; }
        }
        g_idx[m0 + tid] = bi;
    }
}

// ---------------- kernel C: gather z_q (smem-staged, coalesced) -------------
// Block handles 32 consecutive n (same batch). Stage 32 codebook rows into
// smem coalescedly, then write out[b][d][hw] fully coalesced.
__global__ void __launch_bounds__(256)
gather_kernel(const float* __restrict__ z, const float* __restrict__ emb,
              float* __restrict__ out) {
    __shared__ float rows[32][257];   // pad -> conflict-free transpose reads
    __shared__ int   idxs[32];
    __shared__ float red[256];

    const int tid = threadIdx.x;
    const int n0  = blockIdx.x * 32;
    const int b   = n0 >> 10;
    const int hw0 = n0 & 1023;

    if (tid < 32) idxs[tid] = g_idx[n0 + tid];
    __syncthreads();

    // stage 32 rows x 256 floats (each iter: 4 rows, float4 per thread)
    const int rbase = tid >> 6;          // 0..3
    const int c4    = (tid & 63) << 2;   // 0..252
#pragma unroll
    for (int rr = 0; rr < 8; ++rr) {
        int r = rbase + rr * 4;
        float4 v = *(const float4*)(emb + (size_t)idxs[r] * DDIM + c4);
        rows[r][c4]     = v.x;
        rows[r][c4 + 1] = v.y;
        rows[r][c4 + 2] = v.z;
        rows[r][c4 + 3] = v.w;
    }
    __syncthreads();

    const int j  = tid & 31;   // hw offset within block
    const int ds = tid >> 5;   // 8 d's per pass
    float s = 0.f;
    const float* zp = z   + (size_t)b * (DDIM * HW) + hw0 + j;
    float*       op = out + (size_t)b * (DDIM * HW) + hw0 + j;
#pragma unroll 8
    for (int pass = 0; pass < 32; ++pass) {
        int d = pass * 8 + ds;
        float q  = rows[j][d];
        size_t off = (size_t)d * HW;
        float zv = zp[off];
        float df = __fadd_rn(q, -zv);      // fl(z_q - z)
        op[off] = __fadd_rn(zv, df);       // straight-through fl(z + fl(z_q - z))
        s = fmaf(df, df, s);
    }

    red[tid] = s;
    __syncthreads();
#pragma unroll
    for (int o = 128; o; o >>= 1) {
        if (tid < o) red[tid] += red[tid + o];
        __syncthreads();
    }
    if (tid == 0) g_partial[blockIdx.x] = red[0];
}

// ---------------- kernel D: finalize loss (deterministic tree reduce) --------
__global__ void finalize_kernel(float* __restrict__ out) {
    __shared__ float red[256];
    float s = 0.f;
#pragma unroll
    for (int r = 0; r < GATHER_BLOCKS / 256; ++r)
        s += g_partial[threadIdx.x + 256 * r];
    red[threadIdx.x] = s;
    __syncthreads();
#pragma unroll
    for (int o = 128; o; o >>= 1) {
        if (threadIdx.x < o) red[threadIdx.x] += red[threadIdx.x + o];
        __syncthreads();
    }
    if (threadIdx.x == 0) {
        float q = red[0] / (float)NZ;          // /2^23 exact
        out[NZ] = __fadd_rn(q, 0.25f * q);     // loss = q_latent + 0.25*e_latent
    }
}

// ---------------- kernel E: indices as float ----------------
__global__ void idx_out_kernel(float* __restrict__ out) {
    int n = blockIdx.x * 256 + threadIdx.x;
    out[NZ + 1 + n] = (float)g_idx[n];
}

extern "C" void kernel_launch(void* const* d_in, const int* in_sizes, int n_in,
                              void* d_out, int out_size) {
    const float* a0 = (const float*)d_in[0];
    const float* a1 = (const float*)d_in[1];
    const float* z;
    const float* emb;
    if (in_sizes[0] == NZ) { z = a0; emb = a1; }
    else                   { z = a1; emb = a0; }
    float* out = (float*)d_out;

    ek2_kernel<<<128, 256>>>(emb);
    zn2_kernel<<<NN / 256, 256>>>(z);
    vq_argmin_kernel<<<256, 256>>>(z, emb);
    gather_kernel<<<GATHER_BLOCKS, 256>>>(z, emb, out);
    if (out_size > NZ)            finalize_kernel<<<1, 256>>>(out);
    if (out_size >= NZ + 1 + NN)  idx_out_kernel<<<NN / 256, 256>>>(out);
}